// round 4
// baseline (speedup 1.0000x reference)
#include <cuda_runtime.h>
#include <cuda_bf16.h>
#include <cstdint>

// ---------------- problem constants ----------------
#define NE     1024
#define DDIM   64
#define HW     4096
#define NPIX   131072
#define QELEMS (NPIX * DDIM)
#define KTOT   208            // 3*64 + 3 (hn) + 1 pad (to 13*16)
#define KU32   104            // u32 per packed row
#define MT     128            // pixels per CTA
#define NCHUNK 128            // codes per chunk
#define NCH    8
#define KSTEPS 13
#define GAPT   2e-2f

// smem: A tile + 2 B buffers, row stride 432B (27*16 -> conflict-free ldmatrix)
#define RSTRIDE 432
#define ABYTES  (MT * RSTRIDE)        // 55296
#define BBYTES  (NCHUNK * RSTRIDE)    // 55296
#define SM_TOT  (ABYTES + 2 * BBYTES) // 165888

// ---------------- device scratch ----------------
__device__ unsigned g_Bpack[NE * KU32];   // packed codes [code][104 u32]
__device__ float g_codeT[NE * DDIM];      // fp32 codebook [code][dim]
__device__ float g_hn[NE];                // 0.5*||e||^2
__device__ int   g_bidx[NPIX];
__device__ float g_gap[NPIX];
__device__ float g_partial[512];

// ---------------- helpers ----------------
__device__ __forceinline__ unsigned smem_u32(const void* p) {
    unsigned a;
    asm("{ .reg .u64 t; cvta.to.shared.u64 t, %1; cvt.u32.u64 %0, t; }" : "=r"(a) : "l"(p));
    return a;
}
__device__ __forceinline__ void cpasync16(unsigned s, const void* g) {
    asm volatile("cp.async.cg.shared.global [%0], [%1], 16;" :: "r"(s), "l"(g));
}
__device__ __forceinline__ void cpacommit() { asm volatile("cp.async.commit_group;"); }
template <int N> __device__ __forceinline__ void cpawait() {
    asm volatile("cp.async.wait_group %0;" :: "n"(N));
}
__device__ __forceinline__ void ldsm_x4(unsigned& r0, unsigned& r1, unsigned& r2, unsigned& r3,
                                        unsigned addr) {
    asm volatile("ldmatrix.sync.aligned.m8n8.x4.shared.b16 {%0,%1,%2,%3}, [%4];"
                 : "=r"(r0), "=r"(r1), "=r"(r2), "=r"(r3) : "r"(addr));
}
__device__ __forceinline__ void mma16816(float* c, const unsigned* a, const unsigned* b) {
    asm volatile("mma.sync.aligned.m16n8k16.row.col.f32.bf16.bf16.f32 "
                 "{%0,%1,%2,%3}, {%4,%5,%6,%7}, {%8,%9}, {%0,%1,%2,%3};"
                 : "+f"(c[0]), "+f"(c[1]), "+f"(c[2]), "+f"(c[3])
                 : "r"(a[0]), "r"(a[1]), "r"(a[2]), "r"(a[3]), "r"(b[0]), "r"(b[1]));
}

__device__ __forceinline__ unsigned short bfhi(float v) {
    return __bfloat16_as_ushort(__float2bfloat16(v));
}
__device__ __forceinline__ unsigned short bflo(float v) {
    __nv_bfloat16 h = __float2bfloat16(v);
    return __bfloat16_as_ushort(__float2bfloat16(v - __bfloat162float(h)));
}
__device__ __forceinline__ unsigned pk(unsigned short a, unsigned short b) {
    return (unsigned)a | ((unsigned)b << 16);
}

// merge two (best, sec, idx) triples; lower index wins ties
__device__ __forceinline__ void merge3(float& b1, float& s1, int& i1,
                                       float b2, float s2, int i2) {
    if (b2 > b1 || (b2 == b1 && i2 < i1)) {
        s1 = fmaxf(s2, b1);
        b1 = b2; i1 = i2;
    } else {
        s1 = fmaxf(s1, b2);
    }
}

// ---------------------------------------------------------------------------
// packB: codebook -> bf16 rows [e_hi | e_hi | e_lo | -hn1,-hn2,-hn3 | 0 pad]
// embed layout [DDIM, NE]
// ---------------------------------------------------------------------------
__global__ void packB(const float* __restrict__ embed) {
    int j = blockIdx.x * 256 + threadIdx.x;
    if (j >= NE) return;
    float e[DDIM];
    float hn = 0.f;
#pragma unroll
    for (int d = 0; d < DDIM; d++) {
        float v = embed[d * NE + j];
        e[d] = v;
        g_codeT[j * DDIM + d] = v;
        hn += v * v;
    }
    hn *= 0.5f;
    g_hn[j] = hn;
    __nv_bfloat16 h1 = __float2bfloat16(hn);
    float r1 = hn - __bfloat162float(h1);
    __nv_bfloat16 h2 = __float2bfloat16(r1);
    float r2 = r1 - __bfloat162float(h2);
    __nv_bfloat16 h3 = __float2bfloat16(r2);
    unsigned short nh1 = __bfloat16_as_ushort(h1) ^ 0x8000;
    unsigned short nh2 = __bfloat16_as_ushort(h2) ^ 0x8000;
    unsigned short nh3 = __bfloat16_as_ushort(h3) ^ 0x8000;

    unsigned* dst = g_Bpack + (size_t)j * KU32;
#pragma unroll
    for (int pc = 0; pc < KU32; pc++) {
        int k0 = 2 * pc, k1 = k0 + 1;
        unsigned short a, b;
        a = (k0 < 64) ? bfhi(e[k0]) : (k0 < 128) ? bfhi(e[k0 - 64]) : (k0 < 192) ? bflo(e[k0 - 128])
          : (k0 == 192) ? nh1 : (k0 == 193) ? nh2 : (k0 == 194) ? nh3 : (unsigned short)0;
        b = (k1 < 64) ? bfhi(e[k1]) : (k1 < 128) ? bfhi(e[k1 - 64]) : (k1 < 192) ? bflo(e[k1 - 128])
          : (k1 == 192) ? nh1 : (k1 == 193) ? nh2 : (k1 == 194) ? nh3 : (unsigned short)0;
        dst[pc] = pk(a, b);
    }
}

// ---------------------------------------------------------------------------
// GEMM + fused argmax. CTA: 128 pixels x 1024 codes. 8 warps (4 M x 2 N),
// warp tile 32x64, mma.m16n8k16 bf16.
// ---------------------------------------------------------------------------
__global__ void __launch_bounds__(256, 1) vq_mma(const float* __restrict__ x) {
    extern __shared__ char smem[];
    const unsigned sA = smem_u32(smem);
    const unsigned sB = sA + ABYTES;
    const int tid = threadIdx.x, wid = tid >> 5, lane = tid & 31;
    const int warpM = wid >> 1, warpN = wid & 1;
    const int p0 = blockIdx.x * MT;
    const int b = p0 >> 12, hw0 = p0 & 4095;

    // ---- producers: warps 0-3 build A in smem; warps 4-7 cp.async B0,B1 ----
    if (wid < 4) {
        const int t = tid;  // pixel row 0..127
        const float* xb = x + (size_t)b * DDIM * HW + hw0 + t;
        unsigned short hi[DDIM], lo[DDIM];
#pragma unroll
        for (int d = 0; d < DDIM; d++) {
            float v = xb[d * HW];
            hi[d] = bfhi(v);
            lo[d] = bflo(v);
        }
        unsigned rowa = sA + t * RSTRIDE;
        const unsigned ONE2 = pk(0x3F80, 0x3F80);
#pragma unroll
        for (int pc = 0; pc < 32; pc++) {
            unsigned vh = pk(hi[2 * pc], hi[2 * pc + 1]);
            unsigned vl = pk(lo[2 * pc], lo[2 * pc + 1]);
            asm volatile("st.shared.b32 [%0], %1;" :: "r"(rowa + pc * 4), "r"(vh));
            asm volatile("st.shared.b32 [%0], %1;" :: "r"(rowa + (32 + pc) * 4), "r"(vl));
            asm volatile("st.shared.b32 [%0], %1;" :: "r"(rowa + (64 + pc) * 4), "r"(vh));
        }
        asm volatile("st.shared.b32 [%0], %1;" :: "r"(rowa + 96 * 4), "r"(ONE2));
        asm volatile("st.shared.b32 [%0], %1;" :: "r"(rowa + 97 * 4), "r"(pk(0x3F80, 0)));
#pragma unroll
        for (int pc = 98; pc < 108; pc++)  // zero pad through stride (432B = 108 u32)
            asm volatile("st.shared.b32 [%0], %1;" :: "r"(rowa + pc * 4), "r"(0u));
    } else {
        const int t = tid - 128;  // 0..127 -> one code row each
#pragma unroll 1
        for (int c = 0; c < 2; c++) {
            const char* src = (const char*)(g_Bpack + (size_t)(c * NCHUNK + t) * KU32);
            unsigned drow = sB + c * BBYTES + t * RSTRIDE;
#pragma unroll
            for (int q = 0; q < 26; q++)
                cpasync16(drow + q * 16, src + q * 16);
            cpacommit();
        }
    }

    // ---- fragment address precompute ----
    // A (x4): lanes 0-15 rows m..m+15 @k0, lanes 16-31 same rows @k0+8
    const unsigned aBase = sA + (warpM * 32 + (lane & 15)) * RSTRIDE + ((lane >> 4) * 8) * 2;
    // B (x4, two n-tiles): code = n0 + (lane&7) + (lane>=16 ? 8:0), koff = (lane&8)?8:0
    const unsigned bRow = (unsigned)(warpN * 64 + (lane & 7) + ((lane >> 4) << 3));
    const unsigned bKoff = (lane & 8) ? 16u : 0u;

    // per-thread argmax state: slots [mtile t][r: +0/+8]
    float best[2][2] = {{-1e30f, -1e30f}, {-1e30f, -1e30f}};
    float sec[2][2] = {{-1e30f, -1e30f}, {-1e30f, -1e30f}};
    int   bidx[2][2] = {{0, 0}, {0, 0}};

#pragma unroll 1
    for (int c = 0; c < NCH; c++) {
        if (wid >= 4) {
            if (c >= NCH - 2) cpawait<0>(); else cpawait<1>();
        }
        __syncthreads();
        const unsigned Bb = sB + (c & 1) * BBYTES;

        float acc[2][8][4];
#pragma unroll
        for (int t = 0; t < 2; t++)
#pragma unroll
            for (int j = 0; j < 8; j++)
#pragma unroll
                for (int q = 0; q < 4; q++) acc[t][j][q] = 0.f;

#pragma unroll
        for (int ks = 0; ks < KSTEPS; ks++) {
            unsigned af[2][4];
            ldsm_x4(af[0][0], af[0][1], af[0][2], af[0][3], aBase + ks * 32);
            ldsm_x4(af[1][0], af[1][1], af[1][2], af[1][3], aBase + 16 * RSTRIDE + ks * 32);
            unsigned bf[8][2];
#pragma unroll
            for (int p = 0; p < 4; p++) {
                unsigned addr = Bb + (bRow + p * 16) * RSTRIDE + bKoff + ks * 32;
                ldsm_x4(bf[2 * p][0], bf[2 * p][1], bf[2 * p + 1][0], bf[2 * p + 1][1], addr);
            }
#pragma unroll
            for (int t = 0; t < 2; t++)
#pragma unroll
                for (int j = 0; j < 8; j++)
                    mma16816(acc[t][j], af[t], bf[j]);
        }

        // fused argmax epilogue (registers only)
        const int colb = c * NCHUNK + warpN * 64 + (lane & 3) * 2;
#pragma unroll
        for (int t = 0; t < 2; t++)
#pragma unroll
            for (int j = 0; j < 8; j++)
#pragma unroll
                for (int q = 0; q < 4; q++) {
                    float v = acc[t][j][q];
                    int r = q >> 1;               // 0: row g, 1: row g+8
                    int jj = colb + j * 8 + (q & 1);
                    if (v > best[t][r]) {
                        sec[t][r] = best[t][r];
                        best[t][r] = v; bidx[t][r] = jj;
                    } else if (v > sec[t][r]) {
                        sec[t][r] = v;
                    }
                }

        __syncthreads();
        if (c + 2 < NCH && wid >= 4) {
            const int t = tid - 128;
            const char* src = (const char*)(g_Bpack + (size_t)((c + 2) * NCHUNK + t) * KU32);
            unsigned drow = sB + (c & 1) * BBYTES + t * RSTRIDE;
#pragma unroll
            for (int q = 0; q < 26; q++)
                cpasync16(drow + q * 16, src + q * 16);
            cpacommit();
        }
    }

    // ---- reduce across quad lanes (butterfly) ----
#pragma unroll
    for (int t = 0; t < 2; t++)
#pragma unroll
        for (int r = 0; r < 2; r++) {
#pragma unroll
            for (int o = 1; o <= 2; o <<= 1) {
                float ob = __shfl_xor_sync(0xFFFFFFFFu, best[t][r], o);
                float os = __shfl_xor_sync(0xFFFFFFFFu, sec[t][r], o);
                int   oi = __shfl_xor_sync(0xFFFFFFFFu, bidx[t][r], o);
                merge3(best[t][r], sec[t][r], bidx[t][r], ob, os, oi);
            }
        }

    // ---- merge the two warpN halves via smem (reuse A region) ----
    __syncthreads();
    float* mB = (float*)smem;             // [128][2]
    float* mS = mB + 256;
    int*   mI = (int*)(mS + 256);
    if ((lane & 3) == 0) {
        int g = lane >> 2;
#pragma unroll
        for (int t = 0; t < 2; t++)
#pragma unroll
            for (int r = 0; r < 2; r++) {
                int row = warpM * 32 + t * 16 + g + r * 8;
                mB[row * 2 + warpN] = best[t][r];
                mS[row * 2 + warpN] = sec[t][r];
                mI[row * 2 + warpN] = bidx[t][r];
            }
    }
    __syncthreads();
    if (tid < MT) {
        float b0 = mB[tid * 2], s0 = mS[tid * 2];
        int i0 = mI[tid * 2];
        merge3(b0, s0, i0, mB[tid * 2 + 1], mS[tid * 2 + 1], mI[tid * 2 + 1]);
        g_bidx[p0 + tid] = i0;
        g_gap[p0 + tid] = b0 - s0;
    }
}

// ---------------------------------------------------------------------------
// Finalize: exact rescan of ambiguous pixels, gather codes, write output, loss
// ---------------------------------------------------------------------------
__device__ __forceinline__ unsigned sortable(float s) {
    unsigned u = __float_as_uint(s);
    return (u & 0x80000000u) ? ~u : (u | 0x80000000u);
}

__global__ void __launch_bounds__(256) finalize(const float* __restrict__ x,
                                                float* __restrict__ out) {
    __shared__ float sRed[8];
    const int t = threadIdx.x, lane = t & 31;
    const int p = blockIdx.x * 256 + t;
    const int b = p >> 12, hw = p & 4095;
    int idx = g_bidx[p];
    const bool flag = g_gap[p] < GAPT;

    unsigned m = __ballot_sync(0xFFFFFFFFu, flag);
    while (m) {
        int src = __ffs(m) - 1;
        m &= m - 1;
        int pf = __shfl_sync(0xFFFFFFFFu, p, src);
        const float* xf = x + (size_t)(pf >> 12) * DDIM * HW + (pf & 4095);
        float f[DDIM];
#pragma unroll
        for (int d = 0; d < DDIM; d++) f[d] = xf[d * HW];  // broadcast load
        float lb = -1e30f;
        int li = 0;
#pragma unroll 1
        for (int c = 0; c < 32; c++) {
            int j = lane * 32 + c;
            const float4* cr = (const float4*)(g_codeT + j * DDIM);
            float s = 0.f;
#pragma unroll
            for (int kk = 0; kk < 16; kk++) {
                float4 q = cr[kk];
                s += f[4 * kk] * q.x + f[4 * kk + 1] * q.y
                   + f[4 * kk + 2] * q.z + f[4 * kk + 3] * q.w;
            }
            s -= g_hn[j];
            if (s > lb) { lb = s; li = j; }
        }
        unsigned long long key = ((unsigned long long)sortable(lb) << 32) | (unsigned)(1023 - li);
#pragma unroll
        for (int o = 16; o; o >>= 1) {
            unsigned long long ok = __shfl_xor_sync(0xFFFFFFFFu, key, o);
            if (ok > key) key = ok;
        }
        int fidx = 1023 - (int)(key & 0xFFFFFFFFu);
        if (lane == src) idx = fidx;
    }

    const float* xb = x + (size_t)b * DDIM * HW + hw;
    float* ob = out + (size_t)b * DDIM * HW + hw;
    const float4* cr = (const float4*)(g_codeT + idx * DDIM);
    float loss = 0.f;
#pragma unroll
    for (int kk = 0; kk < 16; kk++) {
        float4 q = cr[kk];
        int d = 4 * kk;
        float r;
        ob[(d + 0) * HW] = q.x; r = q.x - xb[(d + 0) * HW]; loss += r * r;
        ob[(d + 1) * HW] = q.y; r = q.y - xb[(d + 1) * HW]; loss += r * r;
        ob[(d + 2) * HW] = q.z; r = q.z - xb[(d + 2) * HW]; loss += r * r;
        ob[(d + 3) * HW] = q.w; r = q.w - xb[(d + 3) * HW]; loss += r * r;
    }
#pragma unroll
    for (int o = 16; o; o >>= 1) loss += __shfl_xor_sync(0xFFFFFFFFu, loss, o);
    if (lane == 0) sRed[t >> 5] = loss;
    __syncthreads();
    if (t == 0) {
        float s = 0.f;
#pragma unroll
        for (int w = 0; w < 8; w++) s += sRed[w];
        g_partial[blockIdx.x] = s;
    }
}

__global__ void fin_kernel(float* __restrict__ out, int last) {
    __shared__ float sRed[16];
    int t = threadIdx.x;  // 512
    float v = g_partial[t];
#pragma unroll
    for (int o = 16; o; o >>= 1) v += __shfl_xor_sync(0xFFFFFFFFu, v, o);
    if ((t & 31) == 0) sRed[t >> 5] = v;
    __syncthreads();
    if (t == 0) {
        double s = 0.0;
#pragma unroll
        for (int w = 0; w < 16; w++) s += (double)sRed[w];
        out[last] = (float)(s / (double)QELEMS);
    }
}

// ---------------------------------------------------------------------------
extern "C" void kernel_launch(void* const* d_in, const int* in_sizes, int n_in,
                              void* d_out, int out_size) {
    const float* x = (const float*)d_in[0];
    const float* embed = (const float*)d_in[1];
    if (n_in >= 2 && in_sizes[0] == NE * DDIM && in_sizes[1] == QELEMS) {
        const float* tmp = x; x = embed; embed = tmp;
    }
    float* out = (float*)d_out;

    static bool attr_set = false;
    if (!attr_set) {
        cudaFuncSetAttribute(vq_mma, cudaFuncAttributeMaxDynamicSharedMemorySize, SM_TOT);
        attr_set = true;
    }

    packB<<<4, 256>>>(embed);
    vq_mma<<<NPIX / MT, 256, SM_TOT>>>(x);
    finalize<<<NPIX / 256, 256>>>(x, out);
    fin_kernel<<<1, 512>>>(out, out_size - 1);
}